// round 10
// baseline (speedup 1.0000x reference)
#include <cuda_runtime.h>
#include <cuda_fp16.h>
#include <cstdint>
#include <math.h>

// ---------------- problem constants ----------------
#define B_  64
#define T_  512
#define H_  1024
#define U_  1024
#define M_  (B_ * T_)          // 32768
#define NBLK 8                 // U_/128 column blocks

// ---------------- GEMM tiling ----------------
#define BM 128
#define BN 128
#define KSTEP 16
#define NK (H_ / KSTEP)        // 64 k-steps
#define TILEB 4096             // one [128 x 32B] swizzled tile
// stage: A32lo | A32hi | A16 | B16  (4 KB each)
#define STAGEB (4 * TILEB)     // 16 KB
#define PIPE 4
#define SMEM_TOTAL (PIPE * STAGEB)   // 65536 B

// ---------------- context tiling ----------------
#define TCH 16                 // t-chunks per batch
#define TSEG (T_ / TCH)        // 32

// ---------------- device scratch ----------------
__device__ __half g_Bh[(size_t)U_ * H_];   // Wh^T as [n][k], fp16
__device__ float g_partial[(size_t)M_ * NBLK];
__device__ float g_ctxp[(size_t)B_ * TCH * H_];   // context partials

// ---------------- helpers ----------------
__device__ __forceinline__ uint32_t smem_u32(const void* p) {
    uint32_t a;
    asm("{ .reg .u64 t; cvta.to.shared.u64 t, %1; cvt.u32.u64 %0, t; }" : "=r"(a) : "l"(p));
    return a;
}
__device__ __forceinline__ void cp16(uint32_t dst, const void* src) {
    asm volatile("cp.async.cg.shared.global [%0], [%1], 16;" :: "r"(dst), "l"(src));
}
__device__ __forceinline__ void cp_commit() { asm volatile("cp.async.commit_group;" ::: "memory"); }
template <int N_> __device__ __forceinline__ void cp_wait() {
    asm volatile("cp.async.wait_group %0;" :: "n"(N_) : "memory");
}
__device__ __forceinline__ void ldsm4(uint32_t* r, uint32_t a) {
    asm volatile("ldmatrix.sync.aligned.m8n8.x4.shared.b16 {%0,%1,%2,%3}, [%4];"
                 : "=r"(r[0]), "=r"(r[1]), "=r"(r[2]), "=r"(r[3]) : "r"(a));
}
__device__ __forceinline__ void mma16816(float* d, const uint32_t* a, uint32_t b0, uint32_t b1) {
    asm volatile(
        "mma.sync.aligned.m16n8k16.row.col.f32.f16.f16.f32 "
        "{%0,%1,%2,%3},{%4,%5,%6,%7},{%8,%9},{%0,%1,%2,%3};"
        : "+f"(d[0]), "+f"(d[1]), "+f"(d[2]), "+f"(d[3])
        : "r"(a[0]), "r"(a[1]), "r"(a[2]), "r"(a[3]), "r"(b0), "r"(b1));
}
__device__ __forceinline__ uint32_t lds128_cvt2(uint32_t addr_lo) {
    return addr_lo;  // placeholder (unused)
}
__device__ __forceinline__ float fast_tanh(float x) {
    float ax = fabsf(x);
    float e  = __expf(2.0f * ax);
    float r  = 1.0f - __fdividef(2.0f, e + 1.0f);
    return copysignf(r, x);
}
// 16B-chunk swizzle within a [128 x 32B] tile (verified conflict-free).
__device__ __forceinline__ uint32_t tile_off(int row, int c) {
    const int r8  = row & 7;
    const int idx = r8 * 2 + (c ^ ((r8 >> 2) & 1));
    return (uint32_t)((row >> 3) * 256 + idx * 16);
}

// ---------------------------------------------------------------------------
// Kernel 0b: transpose Wh [K,N] fp32 -> g_Bh [N,K] fp16
// ---------------------------------------------------------------------------
__global__ __launch_bounds__(256)
void k_convB(const float* __restrict__ Wh)
{
    __shared__ float tile[32][33];
    const int k0 = blockIdx.y * 32, n0 = blockIdx.x * 32;
    const int tx = threadIdx.x, ty = threadIdx.y;   // 32 x 8
#pragma unroll
    for (int r = 0; r < 4; r++)
        tile[ty + r * 8][tx] = Wh[(size_t)(k0 + ty + r * 8) * U_ + n0 + tx];
    __syncthreads();
#pragma unroll
    for (int r = 0; r < 4; r++) {
        int n = n0 + ty + r * 8;
        int k = k0 + tx;
        g_Bh[(size_t)n * H_ + k] = __float2half(tile[tx][ty + r * 8]);
    }
}

// ---------------------------------------------------------------------------
// Kernel 1: fp16 GEMM with IN-KERNEL fp32->fp16 A conversion.
// A is loaded from enc (fp32) into two swizzled 32B tiles, converted in smem
// to the fp16 A tile one pipeline step ahead, then consumed via ldmatrix.
// ---------------------------------------------------------------------------
__global__ __launch_bounds__(256, 2)
void k_gemm_mma(const float* __restrict__ enc,
                const float* __restrict__ bh, const float* __restrict__ Wv)
{
    extern __shared__ char smem[];
    const uint32_t sb = smem_u32(smem);

    const int tid  = threadIdx.x;
    const int warp = tid >> 5;
    const int lane = tid & 31;
    const int g    = lane >> 2;
    const int tig  = lane & 3;
    const int warpM = warp >> 1;
    const int warpN = warp & 1;

    const int rowBase = blockIdx.y * BM;
    const int colBase = blockIdx.x * BN;

    // per-thread load/convert indices
    const int lrow = tid >> 1;
    const int lc   = tid & 1;
    const uint32_t sw = tile_off(lrow, lc);           // chunk within a tile
    const uint32_t sw0 = tile_off(lrow, 0);           // fp16 chunk k0..7
    const uint32_t sw1 = tile_off(lrow, 1);           // fp16 chunk k8..15
    const float* gA = enc + (size_t)(rowBase + lrow) * H_;
    const size_t gRowB = (size_t)(colBase + lrow) * H_ + lc * 8;

    // stage buf offsets
#define A32LO(buf) (sb + (buf) * STAGEB)
#define A32HI(buf) (sb + (buf) * STAGEB + TILEB)
#define A16(buf)   (sb + (buf) * STAGEB + 2 * TILEB)
#define B16(buf)   (sb + (buf) * STAGEB + 3 * TILEB)

#define LOAD_STAGE(KT, BUF)                                                    \
    do {                                                                       \
        const int kk_ = (KT) * KSTEP;                                          \
        cp16(A32LO(BUF) + sw, gA + kk_ + lc * 4);                              \
        cp16(A32HI(BUF) + sw, gA + kk_ + 8 + lc * 4);                          \
        cp16(B16(BUF) + sw, g_Bh + gRowB + (size_t)kk_);                       \
        cp_commit();                                                           \
    } while (0)

    // convert stage: fp32 lo/hi tiles -> fp16 tile
#define CONVERT(BUF)                                                           \
    do {                                                                       \
        float4 lo = *(const float4*)(smem + (A32LO(BUF) - sb) + sw);           \
        float4 hi = *(const float4*)(smem + (A32HI(BUF) - sb) + sw);           \
        __half2 c0 = __floats2half2_rn(lo.x, lo.y);                            \
        __half2 c1 = __floats2half2_rn(lo.z, lo.w);                            \
        __half2 c2 = __floats2half2_rn(hi.x, hi.y);                            \
        __half2 c3 = __floats2half2_rn(hi.z, hi.w);                            \
        uint2 wlo, whi;                                                        \
        wlo.x = *(const uint32_t*)&c0; wlo.y = *(const uint32_t*)&c1;          \
        whi.x = *(const uint32_t*)&c2; whi.y = *(const uint32_t*)&c3;          \
        *(uint2*)(smem + (A16(BUF) - sb) + sw0 + lc * 8) = wlo;                \
        *(uint2*)(smem + (A16(BUF) - sb) + sw1 + lc * 8) = whi;                \
    } while (0)

    // ldmatrix per-lane offsets
    const int sub = lane >> 3, q = lane & 7;
    uint32_t aOff[2];
#pragma unroll
    for (int mi = 0; mi < 2; mi++) {
        const int rowA = warpM * 32 + mi * 16 + ((sub & 1) ? 8 : 0) + q;
        aOff[mi] = tile_off(rowA, sub >> 1);
    }
    uint32_t bOff[4];
#pragma unroll
    for (int nip = 0; nip < 4; nip++) {
        const int rowB = warpN * 64 + nip * 16 + ((sub & 2) ? 8 : 0) + q;
        bOff[nip] = tile_off(rowB, sub & 1);
    }

    float d[2][8][4];
#pragma unroll
    for (int mi = 0; mi < 2; mi++)
#pragma unroll
        for (int ni = 0; ni < 8; ni++)
#pragma unroll
            for (int qq = 0; qq < 4; qq++) d[mi][ni][qq] = 0.0f;

    LOAD_STAGE(0, 0);
    LOAD_STAGE(1, 1);
    LOAD_STAGE(2, 2);

    cp_wait<2>();       // stage 0 arrived
    __syncthreads();
    CONVERT(0);

#pragma unroll 4
    for (int kt = 0; kt < NK; kt++) {
        cp_wait<1>();   // stages <= kt+1 arrived
        __syncthreads();    // fences previous iteration's CONVERT writes
        if (kt + 3 < NK) LOAD_STAGE(kt + 3, (kt + 3) & (PIPE - 1));
        else cp_commit();
        if (kt + 1 < NK) CONVERT((kt + 1) & (PIPE - 1));

        const int buf = kt & (PIPE - 1);
        const uint32_t Ah_s = A16(buf), Bh_s = B16(buf);

        uint32_t ah[2][4];
        ldsm4(ah[0], Ah_s + aOff[0]);
        ldsm4(ah[1], Ah_s + aOff[1]);

#pragma unroll
        for (int nip = 0; nip < 4; nip++) {
            uint32_t b4[4];
            ldsm4(b4, Bh_s + bOff[nip]);
            const int n0 = nip * 2, n1 = n0 + 1;
            mma16816(d[0][n0], ah[0], b4[0], b4[1]);
            mma16816(d[1][n0], ah[1], b4[0], b4[1]);
            mma16816(d[0][n1], ah[0], b4[2], b4[3]);
            mma16816(d[1][n1], ah[1], b4[2], b4[3]);
        }
    }
    __syncthreads();

    float s[2][2] = {{0.f, 0.f}, {0.f, 0.f}};
#pragma unroll
    for (int ni = 0; ni < 8; ni++) {
        const int n0 = colBase + warpN * 64 + ni * 8 + 2 * tig;
        const float bb0 = __ldg(bh + n0), bb1 = __ldg(bh + n0 + 1);
        const float w0  = __ldg(Wv + n0), w1  = __ldg(Wv + n0 + 1);
#pragma unroll
        for (int mi = 0; mi < 2; mi++) {
            s[mi][0] = fmaf(fast_tanh(d[mi][ni][0] + bb0), w0, s[mi][0]);
            s[mi][0] = fmaf(fast_tanh(d[mi][ni][1] + bb1), w1, s[mi][0]);
            s[mi][1] = fmaf(fast_tanh(d[mi][ni][2] + bb0), w0, s[mi][1]);
            s[mi][1] = fmaf(fast_tanh(d[mi][ni][3] + bb1), w1, s[mi][1]);
        }
    }
#pragma unroll
    for (int off = 1; off <= 2; off <<= 1) {
#pragma unroll
        for (int mi = 0; mi < 2; mi++) {
            s[mi][0] += __shfl_xor_sync(0xFFFFFFFFu, s[mi][0], off);
            s[mi][1] += __shfl_xor_sync(0xFFFFFFFFu, s[mi][1], off);
        }
    }
    float* red = (float*)smem;
    if (tig == 0) {
#pragma unroll
        for (int mi = 0; mi < 2; mi++) {
            red[(warpM * 32 + mi * 16 + g) * 2 + warpN]     = s[mi][0];
            red[(warpM * 32 + mi * 16 + 8 + g) * 2 + warpN] = s[mi][1];
        }
    }
    __syncthreads();
    if (tid < BM)
        g_partial[(size_t)(rowBase + tid) * NBLK + blockIdx.x] = red[tid * 2] + red[tid * 2 + 1];
#undef LOAD_STAGE
#undef CONVERT
#undef A32LO
#undef A32HI
#undef A16
#undef B16
}

// ---------------------------------------------------------------------------
// Kernel 2: fused softmax + context partial (reads fp32 enc directly).
// ---------------------------------------------------------------------------
__global__ __launch_bounds__(256)
void k_ctx_fused(const float* __restrict__ enc, float* __restrict__ attn_out)
{
    const int tc  = blockIdx.x;
    const int b   = blockIdx.y;
    const int tid = threadIdx.x;

    __shared__ float w[T_];
    __shared__ float rbuf[8];

    const float* p0 = g_partial + ((size_t)b * T_ + tid) * NBLK;
    const float* p1 = g_partial + ((size_t)b * T_ + tid + 256) * NBLK;
    float s0 = 0.f, s1 = 0.f;
#pragma unroll
    for (int i = 0; i < NBLK; i++) { s0 += p0[i]; s1 += p1[i]; }

    float mx = fmaxf(s0, s1);
#pragma unroll
    for (int o = 16; o > 0; o >>= 1) mx = fmaxf(mx, __shfl_xor_sync(0xFFFFFFFFu, mx, o));
    if ((tid & 31) == 0) rbuf[tid >> 5] = mx;
    __syncthreads();
    mx = rbuf[0];
#pragma unroll
    for (int i = 1; i < 8; i++) mx = fmaxf(mx, rbuf[i]);
    __syncthreads();

    const float e0 = expf(s0 - mx);
    const float e1 = expf(s1 - mx);

    float sm = e0 + e1;
#pragma unroll
    for (int o = 16; o > 0; o >>= 1) sm += __shfl_xor_sync(0xFFFFFFFFu, sm, o);
    if ((tid & 31) == 0) rbuf[tid >> 5] = sm;
    __syncthreads();
    sm = rbuf[0];
#pragma unroll
    for (int i = 1; i < 8; i++) sm += rbuf[i];

    const float inv = __fdividef(1.0f, sm);
    w[tid]       = e0 * inv;
    w[tid + 256] = e1 * inv;
    if (tc == 0) {
        attn_out[b * T_ + tid]       = e0 * inv;
        attn_out[b * T_ + tid + 256] = e1 * inv;
    }
    __syncthreads();

    const int h0 = tid * 4;
    const float* base = enc + ((size_t)b * T_ + tc * TSEG) * H_ + h0;
    float a0 = 0.f, a1 = 0.f, a2 = 0.f, a3 = 0.f;
#pragma unroll 8
    for (int t = 0; t < TSEG; t++) {
        const float wt = w[tc * TSEG + t];
        const float4 v = *(const float4*)(base + (size_t)t * H_);
        a0 = fmaf(wt, v.x, a0);
        a1 = fmaf(wt, v.y, a1);
        a2 = fmaf(wt, v.z, a2);
        a3 = fmaf(wt, v.w, a3);
    }
    float4 r = make_float4(a0, a1, a2, a3);
    *(float4*)(g_ctxp + (size_t)(b * TCH + tc) * H_ + h0) = r;
}

// ---------------------------------------------------------------------------
// Kernel 3: reduce context partials: ctx[b,h] = sum_p g_ctxp[b][p][h]
// ---------------------------------------------------------------------------
__global__ __launch_bounds__(256)
void k_ctx_reduce(float* __restrict__ ctx)
{
    const int i = blockIdx.x * 256 + threadIdx.x;
    const int b = i >> 10, h = i & (H_ - 1);
    float s = 0.f;
#pragma unroll
    for (int p = 0; p < TCH; p++) s += g_ctxp[(size_t)(b * TCH + p) * H_ + h];
    ctx[i] = s;
}

// ---------------------------------------------------------------------------
// Launch. Inputs: dec_hidden, enc_output, Wh, bh, Ws, bs, Wv, bv.
// dec/Ws/bs/bv cancel inside softmax. Output: [ctx (64*1024) | attn (64*512)].
// ---------------------------------------------------------------------------
extern "C" void kernel_launch(void* const* d_in, const int* in_sizes, int n_in,
                              void* d_out, int out_size)
{
    (void)in_sizes; (void)n_in; (void)out_size;
    const float* enc = (const float*)d_in[1];
    const float* Wh  = (const float*)d_in[2];
    const float* bh  = (const float*)d_in[3];
    const float* Wv  = (const float*)d_in[6];

    float* out  = (float*)d_out;
    float* ctx  = out;
    float* attn = out + B_ * H_;

    static bool attr_done = false;
    if (!attr_done) {
        cudaFuncSetAttribute(k_gemm_mma, cudaFuncAttributeMaxDynamicSharedMemorySize, SMEM_TOTAL);
        attr_done = true;
    }

    k_convB<<<dim3(U_ / 32, H_ / 32), dim3(32, 8)>>>(Wh);
    k_gemm_mma<<<dim3(NBLK, M_ / BM), 256, SMEM_TOTAL>>>(enc, bh, Wv);
    k_ctx_fused<<<dim3(TCH, B_), 256>>>(enc, attn);
    k_ctx_reduce<<<(B_ * H_) / 256, 256>>>(ctx);
}